// round 16
// baseline (speedup 1.0000x reference)
#include <cuda_runtime.h>
#include <cuda_bf16.h>
#include <math.h>
#include <stdint.h>

// Problem constants
#define Hdim   3584
#define Bb     8
#define NH     28
#define KVH    4
#define GS     7
#define HD     128
#define MB     16
#define BSZ    256
#define Rr     32          // B*KVH
#define QKVROWS 4608       // 3584 q + 512 k + 512 v
#define SCALE  0.08838834764831845f
#define NEG_INF (-1e30f)
#define NSPLIT 7           // column splits (3584 / 512)

// -------- scratch (device globals, no allocation) --------
__device__ float g_qkvp[NSPLIT * Bb * QKVROWS]; // qkv partials [y][b][vrow]
__device__ float g_part[Rr * MB * GS * HD];     // per-chunk partial PV sums
__device__ float g_ml[Rr * MB * GS * 2];        // per-chunk (m, l)
__device__ float g_attn[Bb * Hdim];             // attention output pre O-proj

// ---- cp.async helpers ----
#define CPA16(dst_u32, src_ptr) \
    asm volatile("cp.async.cg.shared.global [%0], [%1], 16;" :: "r"(dst_u32), "l"(src_ptr))
#define CP_COMMIT() asm volatile("cp.async.commit_group;")
#define CP_WAIT0()  asm volatile("cp.async.wait_group 0;")

// ============================================================
// GEMV core: warp = 2 rows x 512-col slice (y), 8 batches.
// ALL 8 weight float4 loads issued up-front: only ~70 live regs
// at a 128-reg budget, so ptxas cannot be forced into WAR
// register reuse -> per-thread weight MLP = 8 (vs ~1 before).
// ============================================================
__device__ __forceinline__ void gemv2x8(const float4* __restrict__ x4,
                                        const float4* __restrict__ w40,
                                        const float4* __restrict__ w41,
                                        int y, int lane, float acc[2][8]) {
    const int cb = y * 128 + lane;
    float4 w0[4], w1[4];
#pragma unroll
    for (int u = 0; u < 4; u++) {
        w0[u] = w40[cb + u * 32];
        w1[u] = w41[cb + u * 32];
    }

#pragma unroll
    for (int u = 0; u < 4; u++) {
        const int c4 = cb + u * 32;
#pragma unroll
        for (int b = 0; b < 8; b++) {
            const float4 xv = x4[b * 896 + c4];
            acc[0][b] += w0[u].x * xv.x + w0[u].y * xv.y + w0[u].z * xv.z + w0[u].w * xv.w;
            acc[1][b] += w1[u].x * xv.x + w1[u].y * xv.y + w1[u].z * xv.z + w1[u].w * xv.w;
        }
    }

#pragma unroll
    for (int r = 0; r < 2; r++)
#pragma unroll
        for (int b = 0; b < 8; b++) {
#pragma unroll
            for (int off = 16; off; off >>= 1)
                acc[r][b] += __shfl_xor_sync(0xffffffffu, acc[r][b], off);
        }
}

// Fused QKV projection. grid (288, 7), 256 threads. 16 rows/block.
__global__ __launch_bounds__(256, 2) void qkv_gemv(
    const float* __restrict__ hid,
    const float* __restrict__ q_w, const float* __restrict__ q_b,
    const float* __restrict__ k_w, const float* __restrict__ k_b,
    const float* __restrict__ v_w, const float* __restrict__ v_b) {
    const int t = threadIdx.x;
    const int lane = t & 31;
    const int warp = t >> 5;
    const int y = blockIdx.y;
    const int rbase = blockIdx.x * 16 + warp * 2;   // virtual row base

    const float* W; const float* bias; int wrow;
    if (rbase < 3584)      { W = q_w; bias = q_b; wrow = rbase; }
    else if (rbase < 4096) { W = k_w; bias = k_b; wrow = rbase - 3584; }
    else                   { W = v_w; bias = v_b; wrow = rbase - 4096; }

    const float4* w40 = (const float4*)(W + (size_t)(wrow + 0) * Hdim);
    const float4* w41 = (const float4*)(W + (size_t)(wrow + 1) * Hdim);

    float acc[2][8];
#pragma unroll
    for (int r = 0; r < 2; r++)
#pragma unroll
        for (int b = 0; b < 8; b++) acc[r][b] = 0.f;

    gemv2x8((const float4*)hid, w40, w41, y, lane, acc);

    if (lane == 0) {
#pragma unroll
        for (int r = 0; r < 2; r++) {
            const float bv = (y == 0) ? bias[wrow + r] : 0.f;
#pragma unroll
            for (int b = 0; b < 8; b++)
                g_qkvp[(size_t)(y * 8 + b) * QKVROWS + rbase + r] = acc[r][b] + bv;
        }
    }
}

// O projection. grid (224, 7), 256 threads. 16 rows/block.
// Atomic accumulate into out (zeroed earlier by attn_combine).
__global__ __launch_bounds__(256, 2) void o_gemv(const float* __restrict__ o_w,
                                                 float* __restrict__ out) {
    const int t = threadIdx.x;
    const int lane = t & 31;
    const int warp = t >> 5;
    const int y = blockIdx.y;
    const int rbase = blockIdx.x * 16 + warp * 2;

    const float4* w40 = (const float4*)(o_w + (size_t)(rbase + 0) * Hdim);
    const float4* w41 = (const float4*)(o_w + (size_t)(rbase + 1) * Hdim);

    float acc[2][8];
#pragma unroll
    for (int r = 0; r < 2; r++)
#pragma unroll
        for (int b = 0; b < 8; b++) acc[r][b] = 0.f;

    gemv2x8((const float4*)g_attn, w40, w41, y, lane, acc);

    if (lane == 0) {
#pragma unroll
        for (int r = 0; r < 2; r++)
#pragma unroll
            for (int b = 0; b < 8; b++)
                atomicAdd(&out[(size_t)b * Hdim + rbase + r], acc[r][b]);
    }
}

// helper: sum qkv partials for (batch b, virtual row vr)
__device__ __forceinline__ float qkv_sum(int b, int vr) {
    float s = 0.f;
#pragma unroll
    for (int yy = 0; yy < NSPLIT; yy++)
        s += g_qkvp[(size_t)(yy * 8 + b) * QKVROWS + vr];
    return s;
}

// ============================================================
// Attention partial (flash-decode split-K) with fused RoPE.
// grid = (16 chunks, 32 rows), 256 threads, dynamic smem.
// K AND V streamed via cp.async.128 into the rotate-swizzled
// ks buffer (V reuses it after phase 1; V0 staged during softmax).
// ============================================================
// smem floats: ks 16384 | q_s 896 | p_s 1792 | knew 128 | vnew 128 | acc2 896
#define SM_KS    0
#define SM_Q     16384
#define SM_P     (16384 + 896)
#define SM_KNEW  (16384 + 896 + 1792)
#define SM_VNEW  (16384 + 896 + 1792 + 128)
#define SM_ACC2  (16384 + 896 + 1792 + 128 + 128)
#define SMEM_ATTN ((16384 + 896 + 1792 + 128 + 128 + 896) * 4)

// stage 128 rows x 128 floats from SRC4 (float4*) into swizzled ks
#define STAGE_KV(SRC4)                                                             \
    { _Pragma("unroll")                                                            \
      for (int ii = 0; ii < 16; ii++) {                                            \
          const int idx = t + ii * 256;                                            \
          const int row_ = idx >> 5;                                               \
          const int c4_  = idx & 31;                                               \
          const uint32_t dst = ks_base +                                           \
              (uint32_t)((((row_ << 5) + ((c4_ + row_) & 31))) << 4);              \
          CPA16(dst, (SRC4) + idx);                                                \
      }                                                                            \
      CP_COMMIT(); }

__device__ __forceinline__ float ks_read_f(const float* ks, int row, int d) {
    const int c4 = d >> 2;
    const int w = (row << 5) + ((c4 + row) & 31);
    return ks[(w << 2) + (d & 3)];
}

__global__ __launch_bounds__(256, 2) void attn_partial(
        const float* __restrict__ k_pool,
        const float* __restrict__ v_pool,
        const int* __restrict__ block_table,
        const int* __restrict__ cache_seqlens,
        const float* __restrict__ cos_,
        const float* __restrict__ sin_) {
    const int c = blockIdx.x;
    const int r = blockIdx.y;
    const int seqlen = cache_seqlens[r];
    const int base = c * BSZ;
    if (base >= seqlen) return;

    extern __shared__ float sm[];
    float*  ks     = sm + SM_KS;
    float4* ks4    = (float4*)ks;
    float*  q_s    = sm + SM_Q;
    float*  p_s    = sm + SM_P;
    float*  knew_s = sm + SM_KNEW;
    float*  vnew_s = sm + SM_VNEW;
    float*  acc2_s = sm + SM_ACC2;
    const uint32_t ks_base = (uint32_t)__cvta_generic_to_shared(ks);

    const int nvalid = min(BSZ, seqlen - base);
    const int pos = seqlen - 1;
    const int jpos = pos - base;      // in [0,256) ONLY for the last chunk
    const int b = r >> 2;
    const int kvh = r & 3;
    const int blk = block_table[r * MB + c];
    const float* __restrict__ K = k_pool + (size_t)blk * BSZ * HD;
    const float* __restrict__ V = v_pool + (size_t)blk * BSZ * HD;

    const int t = threadIdx.x;
    const float* cb = cos_ + b * HD;
    const float* sb = sin_ + b * HD;

    // ---- build q (7 heads, rope), k_new (rope), v_new from qkv partials ----
    {
        const int qvbase = kvh * GS * HD;
        for (int i = t; i < GS * 64; i += 256) {
            const int g = i >> 6;
            const int d = i & 63;
            const float cc = cb[d], ss = sb[d];
            const float a  = qkv_sum(b, qvbase + g * HD + d);
            const float b2 = qkv_sum(b, qvbase + g * HD + d + 64);
            q_s[g * HD + d]      = a * cc - b2 * ss;
            q_s[g * HD + d + 64] = b2 * cc + a * ss;
        }
        if (t < 64) {   // k_new rope pairs
            const int vr = 3584 + kvh * HD + t;
            const float cc = cb[t], ss = sb[t];
            const float a  = qkv_sum(b, vr);
            const float b2 = qkv_sum(b, vr + 64);
            knew_s[t]      = a * cc - b2 * ss;
            knew_s[t + 64] = b2 * cc + a * ss;
        } else if (t < 192) {  // v_new plain
            const int d = t - 64;
            vnew_s[d] = qkv_sum(b, 4096 + kvh * HD + d);
        }
    }

    // ---- phase 1: QK scores via cp.async-staged swizzled halves ----
    const int jl = t & 127;
    const int hh = t >> 7;
    const bool valid_tok = (t < nvalid);
    float sc[GS];
#pragma unroll
    for (int g = 0; g < GS; g++) sc[g] = 0.f;

    for (int h = 0; h < 2; h++) {
        const int hbase = h * 128;
        if (hbase >= nvalid) break;
        __syncthreads();   // prev-half compute done / q+knew ready

        const float4* Ksrc4 = (const float4*)(K + (size_t)hbase * HD);
        STAGE_KV(Ksrc4)
        CP_WAIT0();
        __syncthreads();

        // substitute rope'd new-token row (post-landing fixup)
        const int jloc = jpos - hbase;
        if (jloc >= 0 && jloc < 128) {
            if (t < 32)
                ks4[(jloc << 5) + ((t + jloc) & 31)] = ((const float4*)knew_s)[t];
            __syncthreads();
        }

        if (hh == h && valid_tok) {
            const float4* q4 = (const float4*)q_s;
            const int jrow = jl;
#pragma unroll 4
            for (int u = 0; u < 32; u++) {
                const float4 kv = ks4[(jrow << 5) + ((u + jrow) & 31)];
#pragma unroll
                for (int g = 0; g < GS; g++) {
                    const float4 qv = q4[g * 32 + u];
                    sc[g] += kv.x * qv.x + kv.y * qv.y + kv.z * qv.z + kv.w * qv.w;
                }
            }
        }
    }
    __syncthreads();   // all K reads done; ks free for V

    // ---- stage V half 0 now; it lands while softmax runs ----
    STAGE_KV((const float4*)V)

    // ---- phase 2: softmax, warp per head ----
#pragma unroll
    for (int g = 0; g < GS; g++)
        p_s[g * 256 + t] = valid_tok ? sc[g] * SCALE : NEG_INF;
    __syncthreads();

    const int lane = t & 31, warp = t >> 5;
    const int rc = r * MB + c;
    if (warp < GS) {
        const int g = warp;
        float v[8];
#pragma unroll
        for (int i = 0; i < 8; i++) v[i] = p_s[g * 256 + lane + i * 32];
        float m = v[0];
#pragma unroll
        for (int i = 1; i < 8; i++) m = fmaxf(m, v[i]);
#pragma unroll
        for (int off = 16; off; off >>= 1)
            m = fmaxf(m, __shfl_xor_sync(0xffffffffu, m, off));
        float l = 0.f;
#pragma unroll
        for (int i = 0; i < 8; i++) {
            const float e = __expf(v[i] - m);
            p_s[g * 256 + lane + i * 32] = e;
            l += e;
        }
#pragma unroll
        for (int off = 16; off; off >>= 1)
            l += __shfl_xor_sync(0xffffffffu, l, off);
        if (lane == 0) {
            g_ml[rc * (GS * 2) + g * 2 + 0] = m;
            g_ml[rc * (GS * 2) + g * 2 + 1] = l;
        }
    }
    CP_WAIT0();
    __syncthreads();   // p_s final AND V half 0 landed

    // ---- phase 3: PV from smem V. thread = (d, half); each half
    //      covers 64 tokens of the staged 128-token V half.
    //      p_s is 0 for invalid tokens, so no bounds checks needed.
    const int d = t & 127;
    const int half = t >> 7;
    float acc[GS];
#pragma unroll
    for (int g = 0; g < GS; g++) acc[g] = 0.f;

    // V half 0 fixup (new token row) — only when jpos is in this half
    if (jpos < 128) {
        if (t < 32)
            ks4[(jpos << 5) + ((t + jpos) & 31)] = ((const float4*)vnew_s)[t];
        __syncthreads();
    }
    {
        const int jb = half * 64;
#pragma unroll 4
        for (int jj = 0; jj < 64; jj += 4) {
            const int rl = jb + jj;
            const float v0 = ks_read_f(ks, rl + 0, d);
            const float v1 = ks_read_f(ks, rl + 1, d);
            const float v2 = ks_read_f(ks, rl + 2, d);
            const float v3 = ks_read_f(ks, rl + 3, d);
#pragma unroll
            for (int g = 0; g < GS; g++) {
                const float4 p = *(const float4*)(p_s + g * 256 + rl);
                acc[g] += p.x * v0 + p.y * v1 + p.z * v2 + p.w * v3;
            }
        }
    }
    if (nvalid > 128) {
        __syncthreads();   // all reads of V half 0 done
        STAGE_KV((const float4*)(V + 128 * HD))
        CP_WAIT0();
        __syncthreads();
        // V half 1 fixup — BOTH bounds required (R13 bug).
        const int jloc = jpos - 128;
        if (jloc >= 0 && jloc < 128) {
            if (t < 32)
                ks4[(jloc << 5) + ((t + jloc) & 31)] = ((const float4*)vnew_s)[t];
            __syncthreads();
        }
        const int jb = half * 64;
#pragma unroll 4
        for (int jj = 0; jj < 64; jj += 4) {
            const int rl = jb + jj;
            const float v0 = ks_read_f(ks, rl + 0, d);
            const float v1 = ks_read_f(ks, rl + 1, d);
            const float v2 = ks_read_f(ks, rl + 2, d);
            const float v3 = ks_read_f(ks, rl + 3, d);
#pragma unroll
            for (int g = 0; g < GS; g++) {
                const float4 p = *(const float4*)(p_s + g * 256 + 128 + rl);
                acc[g] += p.x * v0 + p.y * v1 + p.z * v2 + p.w * v3;
            }
        }
    }

    // combine the two thread-halves
    if (half == 1) {
#pragma unroll
        for (int g = 0; g < GS; g++) acc2_s[g * 128 + d] = acc[g];
    }
    __syncthreads();
    if (half == 0) {
        float* outp = g_part + (size_t)rc * (GS * HD);
#pragma unroll
        for (int g = 0; g < GS; g++)
            outp[g * HD + d] = acc[g] + acc2_s[g * 128 + d];
    }
}

// ============================================================
// Combine split-K partials + zero final out for o_gemv atomics.
// grid = (GS, Rr), 128 threads.  224*128 == 28672 == out size.
// ============================================================
__global__ void attn_combine(const int* __restrict__ cache_seqlens,
                             float* __restrict__ out) {
    const int g = blockIdx.x;
    const int r = blockIdx.y;
    const int d = threadIdx.x;

    out[(blockIdx.y * GS + blockIdx.x) * 128 + d] = 0.f;

    const int seqlen = cache_seqlens[r];
    const int nc = (seqlen + BSZ - 1) >> 8;

    float M = NEG_INF;
    for (int c = 0; c < nc; c++)
        M = fmaxf(M, g_ml[(r * MB + c) * (GS * 2) + g * 2]);
    float L = 0.f, acc = 0.f;
    for (int c = 0; c < nc; c++) {
        const int rc = r * MB + c;
        const float m = g_ml[rc * (GS * 2) + g * 2 + 0];
        const float l = g_ml[rc * (GS * 2) + g * 2 + 1];
        const float w = __expf(m - M);
        L += l * w;
        acc += w * g_part[(size_t)rc * (GS * HD) + g * HD + d];
    }
    const int b = r >> 2, kvh = r & 3;
    g_attn[(size_t)b * Hdim + (kvh * GS + g) * HD + d] = acc / L;
}

// ============================================================
extern "C" void kernel_launch(void* const* d_in, const int* in_sizes, int n_in,
                              void* d_out, int out_size) {
    const float* hid  = (const float*)d_in[0];
    const float* cosw = (const float*)d_in[1];
    const float* sinw = (const float*)d_in[2];
    const float* q_w  = (const float*)d_in[3];
    const float* q_b  = (const float*)d_in[4];
    const float* k_w  = (const float*)d_in[5];
    const float* k_b  = (const float*)d_in[6];
    const float* v_w  = (const float*)d_in[7];
    const float* v_b  = (const float*)d_in[8];
    const float* o_w  = (const float*)d_in[9];
    const float* k_pool = (const float*)d_in[10];
    const float* v_pool = (const float*)d_in[11];
    const int* block_table   = (const int*)d_in[12];
    const int* cache_seqlens = (const int*)d_in[13];
    float* out = (float*)d_out;

    cudaFuncSetAttribute(attn_partial, cudaFuncAttributeMaxDynamicSharedMemorySize, SMEM_ATTN);

    // Fused QKV projections: 4608 rows / 16 per block, 7 col-slices
    qkv_gemv<<<dim3(288, NSPLIT), 256>>>(hid, q_w, q_b, k_w, k_b, v_w, v_b);
    // flash-decode partials (rope + qkv-partial reduce fused inside)
    attn_partial<<<dim3(MB, Rr), 256, SMEM_ATTN>>>(k_pool, v_pool, block_table,
                                                   cache_seqlens, cosw, sinw);
    // combine + zero out
    attn_combine<<<dim3(GS, Rr), 128>>>(cache_seqlens, out);
    // O projection: 3584 rows / 16 per block, 7 col-slices, atomic accumulate
    o_gemv<<<dim3(224, NSPLIT), 256>>>(o_w, out);
}

// round 17
// speedup vs baseline: 1.0523x; 1.0523x over previous
#include <cuda_runtime.h>
#include <cuda_bf16.h>
#include <math.h>
#include <stdint.h>

// Problem constants
#define Hdim   3584
#define Bb     8
#define NH     28
#define KVH    4
#define GS     7
#define HD     128
#define MB     16
#define BSZ    256
#define Rr     32          // B*KVH
#define QKVROWS 4608       // 3584 q + 512 k + 512 v
#define SCALE  0.08838834764831845f
#define NEG_INF (-1e30f)
#define NSPLIT 7           // column splits (3584 / 512)

// -------- scratch (device globals, no allocation) --------
__device__ float g_qkvp[NSPLIT * Bb * QKVROWS]; // qkv partials [y][b][vrow]
__device__ float g_part[Rr * MB * GS * HD];     // per-chunk partial PV sums
__device__ float g_ml[Rr * MB * GS * 2];        // per-chunk (m, l)
__device__ float g_attn[Bb * Hdim];             // attention output pre O-proj

// ---- cp.async helpers ----
#define CPA16(dst_u32, src_ptr) \
    asm volatile("cp.async.cg.shared.global [%0], [%1], 16;" :: "r"(dst_u32), "l"(src_ptr))
#define CP_COMMIT() asm volatile("cp.async.commit_group;")
#define CP_WAIT0()  asm volatile("cp.async.wait_group 0;")

// ============================================================
// GEMV core: warp = 4 rows x 512-col slice (y), 8 batches.
// BOTH prior failure modes fixed simultaneously:
//  - x slice staged to smem via cp.async (zero registers, off
//    the LDG/scoreboard path entirely)
//  - ALL 16 weight LDG.128 front-batched into registers (64
//    regs) under a 128-reg budget -> per-warp weight MLP = 16.
// ============================================================
__device__ __forceinline__ void gemv4x8_smem(const float4* __restrict__ xsrc,
                                             const float4* __restrict__ w40,
                                             const float4* __restrict__ w41,
                                             const float4* __restrict__ w42,
                                             const float4* __restrict__ w43,
                                             float4* xs, int y, int t,
                                             float acc[4][8]) {
    // stage x[8][128] float4 slice via cp.async (coalesced, no regs)
    const uint32_t xs_base = (uint32_t)__cvta_generic_to_shared(xs);
#pragma unroll
    for (int i = 0; i < 4; i++) {
        const int idx = t + i * 256;          // 0..1023
        const uint32_t dst = xs_base + (uint32_t)(idx << 4);
        CPA16(dst, xsrc + (idx >> 7) * 896 + y * 128 + (idx & 127));
    }
    CP_COMMIT();

    // front-batch ALL 16 weight loads (fills while x stages)
    const int lane = t & 31;
    const int cb = y * 128 + lane;
    float4 w0[4], w1[4], w2[4], w3[4];
#pragma unroll
    for (int u = 0; u < 4; u++) {
        w0[u] = w40[cb + u * 32];
        w1[u] = w41[cb + u * 32];
        w2[u] = w42[cb + u * 32];
        w3[u] = w43[cb + u * 32];
    }

    CP_WAIT0();
    __syncthreads();

#pragma unroll
    for (int u = 0; u < 4; u++) {
        const int cs = u * 32 + lane;
#pragma unroll
        for (int b = 0; b < 8; b++) {
            const float4 xv = xs[b * 128 + cs];
            acc[0][b] += w0[u].x * xv.x + w0[u].y * xv.y + w0[u].z * xv.z + w0[u].w * xv.w;
            acc[1][b] += w1[u].x * xv.x + w1[u].y * xv.y + w1[u].z * xv.z + w1[u].w * xv.w;
            acc[2][b] += w2[u].x * xv.x + w2[u].y * xv.y + w2[u].z * xv.z + w2[u].w * xv.w;
            acc[3][b] += w3[u].x * xv.x + w3[u].y * xv.y + w3[u].z * xv.z + w3[u].w * xv.w;
        }
    }

#pragma unroll
    for (int r = 0; r < 4; r++)
#pragma unroll
        for (int b = 0; b < 8; b++) {
#pragma unroll
            for (int off = 16; off; off >>= 1)
                acc[r][b] += __shfl_xor_sync(0xffffffffu, acc[r][b], off);
        }
}

// Fused QKV projection. grid (144, 7), 256 threads. 32 rows/block.
__global__ __launch_bounds__(256, 2) void qkv_gemv(
    const float* __restrict__ hid,
    const float* __restrict__ q_w, const float* __restrict__ q_b,
    const float* __restrict__ k_w, const float* __restrict__ k_b,
    const float* __restrict__ v_w, const float* __restrict__ v_b) {
    __shared__ float4 xs[8 * 128];
    const int t = threadIdx.x;
    const int lane = t & 31;
    const int warp = t >> 5;
    const int y = blockIdx.y;
    const int rbase = blockIdx.x * 32 + warp * 4;   // virtual row base

    const float* W; const float* bias; int wrow;
    if (rbase < 3584)      { W = q_w; bias = q_b; wrow = rbase; }
    else if (rbase < 4096) { W = k_w; bias = k_b; wrow = rbase - 3584; }
    else                   { W = v_w; bias = v_b; wrow = rbase - 4096; }

    const float4* w40 = (const float4*)(W + (size_t)(wrow + 0) * Hdim);
    const float4* w41 = (const float4*)(W + (size_t)(wrow + 1) * Hdim);
    const float4* w42 = (const float4*)(W + (size_t)(wrow + 2) * Hdim);
    const float4* w43 = (const float4*)(W + (size_t)(wrow + 3) * Hdim);

    float acc[4][8];
#pragma unroll
    for (int r = 0; r < 4; r++)
#pragma unroll
        for (int b = 0; b < 8; b++) acc[r][b] = 0.f;

    gemv4x8_smem((const float4*)hid, w40, w41, w42, w43, xs, y, t, acc);

    if (lane == 0) {
#pragma unroll
        for (int r = 0; r < 4; r++) {
            const float bv = (y == 0) ? bias[wrow + r] : 0.f;
#pragma unroll
            for (int b = 0; b < 8; b++)
                g_qkvp[(size_t)(y * 8 + b) * QKVROWS + rbase + r] = acc[r][b] + bv;
        }
    }
}

// O projection. grid (112, 7), 256 threads. 32 rows/block.
// Atomic accumulate into out (zeroed earlier by attn_combine).
__global__ __launch_bounds__(256, 2) void o_gemv(const float* __restrict__ o_w,
                                                 float* __restrict__ out) {
    __shared__ float4 xs[8 * 128];
    const int t = threadIdx.x;
    const int lane = t & 31;
    const int warp = t >> 5;
    const int y = blockIdx.y;
    const int rbase = blockIdx.x * 32 + warp * 4;

    const float4* w40 = (const float4*)(o_w + (size_t)(rbase + 0) * Hdim);
    const float4* w41 = (const float4*)(o_w + (size_t)(rbase + 1) * Hdim);
    const float4* w42 = (const float4*)(o_w + (size_t)(rbase + 2) * Hdim);
    const float4* w43 = (const float4*)(o_w + (size_t)(rbase + 3) * Hdim);

    float acc[4][8];
#pragma unroll
    for (int r = 0; r < 4; r++)
#pragma unroll
        for (int b = 0; b < 8; b++) acc[r][b] = 0.f;

    gemv4x8_smem((const float4*)g_attn, w40, w41, w42, w43, xs, y, t, acc);

    if (lane == 0) {
#pragma unroll
        for (int r = 0; r < 4; r++)
#pragma unroll
            for (int b = 0; b < 8; b++)
                atomicAdd(&out[(size_t)b * Hdim + rbase + r], acc[r][b]);
    }
}

// helper: sum qkv partials for (batch b, virtual row vr)
__device__ __forceinline__ float qkv_sum(int b, int vr) {
    float s = 0.f;
#pragma unroll
    for (int yy = 0; yy < NSPLIT; yy++)
        s += g_qkvp[(size_t)(yy * 8 + b) * QKVROWS + vr];
    return s;
}

// ============================================================
// Attention partial (flash-decode split-K) with fused RoPE.
// grid = (16 chunks, 32 rows), 256 threads, dynamic smem.
// K AND V streamed via cp.async.128 into the rotate-swizzled
// ks buffer. K half 0 is staged BEFORE the prologue so its
// latency hides under the rope/qkv_sum work.
// ============================================================
// smem floats: ks 16384 | q_s 896 | p_s 1792 | knew 128 | vnew 128 | acc2 896
#define SM_KS    0
#define SM_Q     16384
#define SM_P     (16384 + 896)
#define SM_KNEW  (16384 + 896 + 1792)
#define SM_VNEW  (16384 + 896 + 1792 + 128)
#define SM_ACC2  (16384 + 896 + 1792 + 128 + 128)
#define SMEM_ATTN ((16384 + 896 + 1792 + 128 + 128 + 896) * 4)

// stage 128 rows x 128 floats from SRC4 (float4*) into swizzled ks
#define STAGE_KV(SRC4)                                                             \
    { _Pragma("unroll")                                                            \
      for (int ii = 0; ii < 16; ii++) {                                            \
          const int idx = t + ii * 256;                                            \
          const int row_ = idx >> 5;                                               \
          const int c4_  = idx & 31;                                               \
          const uint32_t dst = ks_base +                                           \
              (uint32_t)((((row_ << 5) + ((c4_ + row_) & 31))) << 4);              \
          CPA16(dst, (SRC4) + idx);                                                \
      }                                                                            \
      CP_COMMIT(); }

__device__ __forceinline__ float ks_read_f(const float* ks, int row, int d) {
    const int c4 = d >> 2;
    const int w = (row << 5) + ((c4 + row) & 31);
    return ks[(w << 2) + (d & 3)];
}

__global__ __launch_bounds__(256, 2) void attn_partial(
        const float* __restrict__ k_pool,
        const float* __restrict__ v_pool,
        const int* __restrict__ block_table,
        const int* __restrict__ cache_seqlens,
        const float* __restrict__ cos_,
        const float* __restrict__ sin_) {
    const int c = blockIdx.x;
    const int r = blockIdx.y;
    const int seqlen = cache_seqlens[r];
    const int base = c * BSZ;
    if (base >= seqlen) return;

    extern __shared__ float sm[];
    float*  ks     = sm + SM_KS;
    float4* ks4    = (float4*)ks;
    float*  q_s    = sm + SM_Q;
    float*  p_s    = sm + SM_P;
    float*  knew_s = sm + SM_KNEW;
    float*  vnew_s = sm + SM_VNEW;
    float*  acc2_s = sm + SM_ACC2;
    const uint32_t ks_base = (uint32_t)__cvta_generic_to_shared(ks);

    const int nvalid = min(BSZ, seqlen - base);
    const int pos = seqlen - 1;
    const int jpos = pos - base;      // in [0,256) ONLY for the last chunk
    const int b = r >> 2;
    const int kvh = r & 3;
    const int blk = block_table[r * MB + c];
    const float* __restrict__ K = k_pool + (size_t)blk * BSZ * HD;
    const float* __restrict__ V = v_pool + (size_t)blk * BSZ * HD;

    const int t = threadIdx.x;
    const float* cb = cos_ + b * HD;
    const float* sb = sin_ + b * HD;

    // ---- stage K half 0 FIRST: latency hides under the prologue ----
    STAGE_KV((const float4*)K)

    // ---- build q (7 heads, rope), k_new (rope), v_new from qkv partials ----
    {
        const int qvbase = kvh * GS * HD;
        for (int i = t; i < GS * 64; i += 256) {
            const int g = i >> 6;
            const int d = i & 63;
            const float cc = cb[d], ss = sb[d];
            const float a  = qkv_sum(b, qvbase + g * HD + d);
            const float b2 = qkv_sum(b, qvbase + g * HD + d + 64);
            q_s[g * HD + d]      = a * cc - b2 * ss;
            q_s[g * HD + d + 64] = b2 * cc + a * ss;
        }
        if (t < 64) {   // k_new rope pairs
            const int vr = 3584 + kvh * HD + t;
            const float cc = cb[t], ss = sb[t];
            const float a  = qkv_sum(b, vr);
            const float b2 = qkv_sum(b, vr + 64);
            knew_s[t]      = a * cc - b2 * ss;
            knew_s[t + 64] = b2 * cc + a * ss;
        } else if (t < 192) {  // v_new plain
            const int d = t - 64;
            vnew_s[d] = qkv_sum(b, 4096 + kvh * HD + d);
        }
    }

    // ---- phase 1: QK scores ----
    const int jl = t & 127;
    const int hh = t >> 7;
    const bool valid_tok = (t < nvalid);
    float sc[GS];
#pragma unroll
    for (int g = 0; g < GS; g++) sc[g] = 0.f;

    for (int h = 0; h < 2; h++) {
        const int hbase = h * 128;
        if (hbase >= nvalid) break;
        if (h == 1) {
            __syncthreads();   // h=0 compute done; ks reusable
            STAGE_KV((const float4*)(K + 128 * HD))
        }
        CP_WAIT0();
        __syncthreads();       // K half landed (+ prologue visible for h=0)

        // substitute rope'd new-token row (post-landing fixup)
        const int jloc = jpos - hbase;
        if (jloc >= 0 && jloc < 128) {
            if (t < 32)
                ks4[(jloc << 5) + ((t + jloc) & 31)] = ((const float4*)knew_s)[t];
            __syncthreads();
        }

        if (hh == h && valid_tok) {
            const float4* q4 = (const float4*)q_s;
            const int jrow = jl;
#pragma unroll 4
            for (int u = 0; u < 32; u++) {
                const float4 kv = ks4[(jrow << 5) + ((u + jrow) & 31)];
#pragma unroll
                for (int g = 0; g < GS; g++) {
                    const float4 qv = q4[g * 32 + u];
                    sc[g] += kv.x * qv.x + kv.y * qv.y + kv.z * qv.z + kv.w * qv.w;
                }
            }
        }
    }
    __syncthreads();   // all K reads done; ks free for V

    // ---- stage V half 0 now; it lands while softmax runs ----
    STAGE_KV((const float4*)V)

    // ---- phase 2: softmax, warp per head ----
#pragma unroll
    for (int g = 0; g < GS; g++)
        p_s[g * 256 + t] = valid_tok ? sc[g] * SCALE : NEG_INF;
    __syncthreads();

    const int lane = t & 31, warp = t >> 5;
    const int rc = r * MB + c;
    if (warp < GS) {
        const int g = warp;
        float v[8];
#pragma unroll
        for (int i = 0; i < 8; i++) v[i] = p_s[g * 256 + lane + i * 32];
        float m = v[0];
#pragma unroll
        for (int i = 1; i < 8; i++) m = fmaxf(m, v[i]);
#pragma unroll
        for (int off = 16; off; off >>= 1)
            m = fmaxf(m, __shfl_xor_sync(0xffffffffu, m, off));
        float l = 0.f;
#pragma unroll
        for (int i = 0; i < 8; i++) {
            const float e = __expf(v[i] - m);
            p_s[g * 256 + lane + i * 32] = e;
            l += e;
        }
#pragma unroll
        for (int off = 16; off; off >>= 1)
            l += __shfl_xor_sync(0xffffffffu, l, off);
        if (lane == 0) {
            g_ml[rc * (GS * 2) + g * 2 + 0] = m;
            g_ml[rc * (GS * 2) + g * 2 + 1] = l;
        }
    }
    CP_WAIT0();
    __syncthreads();   // p_s final AND V half 0 landed

    // ---- phase 3: PV from smem V. thread = (d, half); each half
    //      covers 64 tokens of the staged 128-token V half.
    //      p_s is 0 for invalid tokens, so no bounds checks needed.
    const int d = t & 127;
    const int half = t >> 7;
    float acc[GS];
#pragma unroll
    for (int g = 0; g < GS; g++) acc[g] = 0.f;

    // V half 0 fixup (new token row) — only when jpos is in this half
    if (jpos < 128) {
        if (t < 32)
            ks4[(jpos << 5) + ((t + jpos) & 31)] = ((const float4*)vnew_s)[t];
        __syncthreads();
    }
    {
        const int jb = half * 64;
#pragma unroll 4
        for (int jj = 0; jj < 64; jj += 4) {
            const int rl = jb + jj;
            const float v0 = ks_read_f(ks, rl + 0, d);
            const float v1 = ks_read_f(ks, rl + 1, d);
            const float v2 = ks_read_f(ks, rl + 2, d);
            const float v3 = ks_read_f(ks, rl + 3, d);
#pragma unroll
            for (int g = 0; g < GS; g++) {
                const float4 p = *(const float4*)(p_s + g * 256 + rl);
                acc[g] += p.x * v0 + p.y * v1 + p.z * v2 + p.w * v3;
            }
        }
    }
    if (nvalid > 128) {
        __syncthreads();   // all reads of V half 0 done
        STAGE_KV((const float4*)(V + 128 * HD))
        CP_WAIT0();
        __syncthreads();
        // V half 1 fixup — BOTH bounds required (R13 bug).
        const int jloc = jpos - 128;
        if (jloc >= 0 && jloc < 128) {
            if (t < 32)
                ks4[(jloc << 5) + ((t + jloc) & 31)] = ((const float4*)vnew_s)[t];
            __syncthreads();
        }
        const int jb = half * 64;
#pragma unroll 4
        for (int jj = 0; jj < 64; jj += 4) {
            const int rl = jb + jj;
            const float v0 = ks_read_f(ks, rl + 0, d);
            const float v1 = ks_read_f(ks, rl + 1, d);
            const float v2 = ks_read_f(ks, rl + 2, d);
            const float v3 = ks_read_f(ks, rl + 3, d);
#pragma unroll
            for (int g = 0; g < GS; g++) {
                const float4 p = *(const float4*)(p_s + g * 256 + 128 + rl);
                acc[g] += p.x * v0 + p.y * v1 + p.z * v2 + p.w * v3;
            }
        }
    }

    // combine the two thread-halves
    if (half == 1) {
#pragma unroll
        for (int g = 0; g < GS; g++) acc2_s[g * 128 + d] = acc[g];
    }
    __syncthreads();
    if (half == 0) {
        float* outp = g_part + (size_t)rc * (GS * HD);
#pragma unroll
        for (int g = 0; g < GS; g++)
            outp[g * HD + d] = acc[g] + acc2_s[g * 128 + d];
    }
}

// ============================================================
// Combine split-K partials + zero final out for o_gemv atomics.
// grid = (GS, Rr), 128 threads.  224*128 == 28672 == out size.
// ============================================================
__global__ void attn_combine(const int* __restrict__ cache_seqlens,
                             float* __restrict__ out) {
    const int g = blockIdx.x;
    const int r = blockIdx.y;
    const int d = threadIdx.x;

    out[(blockIdx.y * GS + blockIdx.x) * 128 + d] = 0.f;

    const int seqlen = cache_seqlens[r];
    const int nc = (seqlen + BSZ - 1) >> 8;

    float M = NEG_INF;
    for (int c = 0; c < nc; c++)
        M = fmaxf(M, g_ml[(r * MB + c) * (GS * 2) + g * 2]);
    float L = 0.f, acc = 0.f;
    for (int c = 0; c < nc; c++) {
        const int rc = r * MB + c;
        const float m = g_ml[rc * (GS * 2) + g * 2 + 0];
        const float l = g_ml[rc * (GS * 2) + g * 2 + 1];
        const float w = __expf(m - M);
        L += l * w;
        acc += w * g_part[(size_t)rc * (GS * HD) + g * HD + d];
    }
    const int b = r >> 2, kvh = r & 3;
    g_attn[(size_t)b * Hdim + (kvh * GS + g) * HD + d] = acc / L;
}

// ============================================================
extern "C" void kernel_launch(void* const* d_in, const int* in_sizes, int n_in,
                              void* d_out, int out_size) {
    const float* hid  = (const float*)d_in[0];
    const float* cosw = (const float*)d_in[1];
    const float* sinw = (const float*)d_in[2];
    const float* q_w  = (const float*)d_in[3];
    const float* q_b  = (const float*)d_in[4];
    const float* k_w  = (const float*)d_in[5];
    const float* k_b  = (const float*)d_in[6];
    const float* v_w  = (const float*)d_in[7];
    const float* v_b  = (const float*)d_in[8];
    const float* o_w  = (const float*)d_in[9];
    const float* k_pool = (const float*)d_in[10];
    const float* v_pool = (const float*)d_in[11];
    const int* block_table   = (const int*)d_in[12];
    const int* cache_seqlens = (const int*)d_in[13];
    float* out = (float*)d_out;

    cudaFuncSetAttribute(attn_partial, cudaFuncAttributeMaxDynamicSharedMemorySize, SMEM_ATTN);

    // Fused QKV projections: 4608 rows / 32 per block, 7 col-slices
    qkv_gemv<<<dim3(144, NSPLIT), 256>>>(hid, q_w, q_b, k_w, k_b, v_w, v_b);
    // flash-decode partials (rope + qkv-partial reduce fused inside)
    attn_partial<<<dim3(MB, Rr), 256, SMEM_ATTN>>>(k_pool, v_pool, block_table,
                                                   cache_seqlens, cosw, sinw);
    // combine + zero out
    attn_combine<<<dim3(GS, Rr), 128>>>(cache_seqlens, out);
    // O projection: 3584 rows / 32 per block, 7 col-slices, atomic accumulate
    o_gemv<<<dim3(112, NSPLIT), 256>>>(o_w, out);
}